// round 5
// baseline (speedup 1.0000x reference)
#include <cuda_runtime.h>
#include <math.h>

// Problem constants
#define CC      50
#define HID     64
#define NB      10
#define NPATHS  5
#define NLAYERS 6
#define BB      64
#define LL      514
#define TT      512
#define NT      (BB*TT)
#define MAXR    0.06f
#define HALFBAR 0.05f
#define PI_F    3.14159265358979f

// Kernel config: 4 warps/block, 4 triplets per warp, 3 blocks/SM target
#define TRIPW    4
#define WPB      4
#define NTHREADS 128
#define TPB      (WPB*TRIPW)      // 16 triplets per block
#define NBLOCKS  (NT/TPB)         // 2048

// Shared memory layout (float offsets)
// phase A: Wr1s [0,768), Wr2s(cols 0..99) [768,7168)
// phase B: pair-transposed WsT [0,2600) WgT [2600,5200) WvT [5200,7800)
//          (pad pair-row p=25 of WvT = [7700,7800) zeroed once at start;
//           WsT/WgT pad rows hold stale-but-finite phase-A data)
#define WSS_OFF    0
#define WGS_OFF    2600
#define WVS_OFF    5200
#define WR2_OFF    768
#define OFF_HVT    7800
#define HVT_TRIP   624            // 12 rows * 52 (3 H rows + 9 VT rows)
#define SMEM_FLOATS (OFF_HVT + TPB*HVT_TRIP)   // 17784
#define SMEM_BYTES (SMEM_FLOATS*4)             // 71136

typedef unsigned long long u64;

__device__ float g_s1[NLAYERS][CC];
__device__ float g_wbar[NLAYERS][NPATHS*CC];

__device__ __forceinline__ float siluf(float x){ return x/(1.f+__expf(-x)); }
__device__ __forceinline__ float sigmf(float x){ return 1.f/(1.f+__expf(-x)); }
__device__ __forceinline__ u64 fma2(u64 a, u64 b, u64 c){
    u64 d; asm("fma.rn.f32x2 %0, %1, %2, %3;" : "=l"(d) : "l"(a), "l"(b), "l"(c));
    return d;
}
__device__ __forceinline__ float2 unpack2(u64 a){
    float2 r; asm("mov.b64 {%0,%1}, %2;" : "=f"(r.x), "=f"(r.y) : "l"(a));
    return r;
}

// ---------------------------------------------------------------------------
__global__ void e3nn_precompute(const float* __restrict__ W_embed,
                                const float* __restrict__ Wr1,
                                const float* __restrict__ br1,
                                const float* __restrict__ Wr2,
                                const float* __restrict__ Ws)
{
    __shared__ float s1[CC], s1n[CC], hid[HID], emb[NB+2];
    __shared__ float fc0s;
    int tid = threadIdx.x;
    if (tid < CC) s1[tid] = W_embed[tid] + W_embed[CC + tid];
    if (tid == 0) {
        const float r = HALFBAR;
        float tt = fminf(fmaxf(r/MAXR, 0.f), 1.f);
        float fc = 0.5f*(cosf(PI_F*tt) + 1.f);
        fc0s = fc;
        const float width = MAXR/(float)(NB-1);
        for (int i = 0; i < NB; i++) {
            float ci = MAXR*(float)i/(float)(NB-1);
            float d  = (r - ci)/width;
            emb[i]   = __expf(-d*d)*fc;
        }
        emb[NB]   = 0.f;
        emb[NB+1] = 1.f;
    }
    __syncthreads();
    for (int l = 0; l < NLAYERS; l++) {
        if (tid < CC) g_s1[l][tid] = s1[tid];
        if (tid < HID) {
            float acc = br1[l*HID + tid];
            #pragma unroll
            for (int i = 0; i < NB+2; i++) acc += emb[i]*Wr1[(l*(NB+2)+i)*HID + tid];
            hid[tid] = siluf(acc);
        }
        if (tid < CC) {
            float acc = 0.f;
            for (int c = 0; c < CC; c++) acc += s1[c]*Ws[(l*CC + c)*CC + tid];
            s1n[tid] = siluf(acc);
        }
        __syncthreads();
        if (tid < NPATHS*CC) {
            float acc = 0.f;
            for (int j = 0; j < HID; j++) acc += hid[j]*Wr2[(l*HID + j)*(NPATHS*CC) + tid];
            g_wbar[l][tid] = acc*fc0s;
        }
        if (tid < CC) s1[tid] = s1n[tid];
        __syncthreads();
    }
}

// ---------------------------------------------------------------------------
__global__ void __launch_bounds__(NTHREADS, 3) e3nn_main(
    const float* __restrict__ y,
    const float* __restrict__ W_embed,
    const float* __restrict__ Wr1,
    const float* __restrict__ br1,
    const float* __restrict__ Wr2,
    const float* __restrict__ Ws,
    const float* __restrict__ Wv,
    const float* __restrict__ Wg,
    const float* __restrict__ W_out,
    float* __restrict__ outp)
{
    extern __shared__ float sm[];
    const int tid  = threadIdx.x;
    const int w    = tid >> 5;
    const int lane = tid & 31;
    const int k    = lane;
    const bool act = (k < 25);
    const int c0   = 2*k;
    const int c1   = c0 + 1;

    const int gbase = blockIdx.x*TPB + w*TRIPW;
    float* hbW = sm + OFF_HVT + (w*TRIPW)*HVT_TRIP;   // warp's 4 triplet slots

    // zero WvT pad pair-row once (never overwritten afterwards)
    for (int i = tid; i < 100; i += NTHREADS) sm[7700 + i] = 0.f;

    // ---- geometry init: lanes 0..3 each handle one triplet; emb kept in regs ----
    float myUIx=0.f, myUIy=0.f, myU3x=0.f, myU3y=0.f, myFc=0.f;
    float eb[NB+2];
    #pragma unroll
    for (int i = 0; i < NB+2; i++) eb[i] = 0.f;
    if (lane < TRIPW) {
        int g = gbase + lane;
        int b = g >> 9;
        int t = g & 511;
        const float* yb = y + ((size_t)b*LL + t)*6;
        float p0x = yb[0],  p0y = yb[1];
        float p1x = yb[6],  p1y = yb[7];
        float a   = yb[8];
        float ex = p0x - p1x, ey = p0y - p1y;
        float r  = sqrtf(ex*ex + ey*ey);
        float inv = 1.f/(r + 1e-12f);
        myUIx = ex*inv; myUIy = ey*inv;
        myU3x = sinf(a); myU3y = -cosf(a);
        float tt = fminf(fmaxf(r/MAXR, 0.f), 1.f);
        myFc = 0.5f*(cosf(PI_F*tt) + 1.f);
        const float width = MAXR/(float)(NB-1);
        #pragma unroll
        for (int i = 0; i < NB; i++) {
            float ci = MAXR*(float)i/(float)(NB-1);
            float d  = (r - ci)/width;
            eb[i]    = __expf(-d*d)*myFc;
        }
        eb[NB]   = 1.f;
        eb[NB+1] = 0.f;
    }
    float uIx[TRIPW], uIy[TRIPW], u3x[TRIPW], u3y[TRIPW], fcT[TRIPW];
    #pragma unroll
    for (int t = 0; t < TRIPW; t++) {
        uIx[t] = __shfl_sync(0xffffffffu, myUIx, t);
        uIy[t] = __shfl_sync(0xffffffffu, myUIy, t);
        u3x[t] = __shfl_sync(0xffffffffu, myU3x, t);
        u3y[t] = __shfl_sync(0xffffffffu, myU3y, t);
        fcT[t] = __shfl_sync(0xffffffffu, myFc,  t);
    }

    // ---- register state ----
    float s[TRIPW][3][2];
    float v[TRIPW][3][2][3];
    #pragma unroll
    for (int t = 0; t < TRIPW; t++)
        #pragma unroll
        for (int n = 0; n < 3; n++)
            #pragma unroll
            for (int q = 0; q < 2; q++) {
                s[t][n][q] = 0.f;
                v[t][n][q][0] = v[t][n][q][1] = v[t][n][q][2] = 0.f;
            }
    if (act) {
        float e00 = W_embed[c0],      e01 = W_embed[c1];
        float e10 = W_embed[CC+c0],   e11 = W_embed[CC+c1];
        float e20 = W_embed[2*CC+c0], e21 = W_embed[2*CC+c1];
        #pragma unroll
        for (int t = 0; t < TRIPW; t++) {
            s[t][0][0] = e00 + e20;  s[t][0][1] = e01 + e21;
            s[t][1][0] = e00 + e10;  s[t][1][1] = e01 + e11;
            s[t][2][0] = e00 + e20;  s[t][2][1] = e01 + e21;
        }
    }

    for (int l = 0; l < NLAYERS; l++) {
        __syncthreads();
        // ---- Phase A staging: Wr1[l] (768) + Wr2[l][:,0:100] (6400) ----
        {
            const float4* s1p = (const float4*)(Wr1 + (size_t)l*(NB+2)*HID);
            float4* d1 = (float4*)sm;
            for (int i = tid; i < 192; i += NTHREADS) d1[i] = s1p[i];
            const float* src2 = Wr2 + (size_t)l*HID*(NPATHS*CC);
            float* dst2 = sm + WR2_OFF;
            for (int idx = tid; idx < HID*100; idx += NTHREADS) {
                int j = idx/100, o = idx - j*100;
                dst2[idx] = src2[j*(NPATHS*CC) + o];
            }
        }
        __syncthreads();
        // ---- hid per triplet (emb broadcast via shfl; HIDS aliased in hbW[0,256)) ----
        {
            float a0[TRIPW], a1[TRIPW];
            float b0 = br1[l*HID + lane];
            float b1 = br1[l*HID + lane + 32];
            #pragma unroll
            for (int t = 0; t < TRIPW; t++) { a0[t] = b0; a1[t] = b1; }
            #pragma unroll
            for (int i = 0; i < NB+2; i++) {
                float w0v = sm[i*HID + lane];
                float w1v = sm[i*HID + lane + 32];
                float ev  = eb[i];
                #pragma unroll
                for (int t = 0; t < TRIPW; t++) {
                    float e = __shfl_sync(0xffffffffu, ev, t);
                    a0[t] += e*w0v;
                    a1[t] += e*w1v;
                }
            }
            #pragma unroll
            for (int t = 0; t < TRIPW; t++) {
                hbW[t*64 + lane]      = siluf(a0[t]);
                hbW[t*64 + lane + 32] = siluf(a1[t]);
            }
        }
        __syncwarp();
        // ---- inter-edge weights (paths 0,1; v_src=0 kills paths 2..4) ----
        float wi[TRIPW][4];
        #pragma unroll
        for (int t = 0; t < TRIPW; t++)
            wi[t][0]=wi[t][1]=wi[t][2]=wi[t][3]=0.f;
        if (act) {
            #pragma unroll 1
            for (int j4 = 0; j4 < HID; j4 += 4) {
                float4 hv[TRIPW];
                #pragma unroll
                for (int t = 0; t < TRIPW; t++)
                    hv[t] = *(const float4*)&hbW[t*64 + j4];
                #pragma unroll
                for (int jo = 0; jo < 4; jo++) {
                    float2 wa = *(const float2*)&sm[WR2_OFF + (j4+jo)*100 + c0];
                    float2 wc = *(const float2*)&sm[WR2_OFF + (j4+jo)*100 + 50 + c0];
                    #pragma unroll
                    for (int t = 0; t < TRIPW; t++) {
                        float hj = (jo==0)?hv[t].x:(jo==1)?hv[t].y:(jo==2)?hv[t].z:hv[t].w;
                        wi[t][0] += hj*wa.x;
                        wi[t][1] += hj*wa.y;
                        wi[t][2] += hj*wc.x;
                        wi[t][3] += hj*wc.y;
                    }
                }
            }
            #pragma unroll
            for (int t = 0; t < TRIPW; t++) {
                wi[t][0]*=fcT[t]; wi[t][1]*=fcT[t]; wi[t][2]*=fcT[t]; wi[t][3]*=fcT[t];
            }
        }
        __syncwarp();   // wi reads of HIDS done before messages overwrite hbW
        // ---- messages -> hb (all 12 rows fully rewritten; pads set to 0) ----
        #pragma unroll
        for (int i = lane; i < 96; i += 32) {   // 4 trip * 12 rows * 2 pad slots
            int t  = i/24;
            int rm = i - t*24;
            hbW[t*HVT_TRIP + (rm>>1)*52 + 50 + (rm&1)] = 0.f;
        }
        if (act) {
            float wb0[2], wb1[2], wb2[2], wb3[2], wb4[2], s1v[2];
            #pragma unroll
            for (int q = 0; q < 2; q++) {
                int cq = c0 + q;
                wb0[q] = g_wbar[l][cq];
                wb1[q] = g_wbar[l][50+cq];
                wb2[q] = g_wbar[l][100+cq];
                wb3[q] = g_wbar[l][150+cq];
                wb4[q] = g_wbar[l][200+cq];
                s1v[q] = g_s1[l][cq];
            }
            #pragma unroll
            for (int t = 0; t < TRIPW; t++) {
                float* hb = hbW + t*HVT_TRIP;
                float H3[2], H4[2], H5[2];
                float V3[2][3], V4[2][3], V5[2][3];
                float ux = u3x[t], uy = u3y[t];
                #pragma unroll
                for (int q = 0; q < 2; q++) {
                    float s4  = s[t][1][q];
                    float v4x = v[t][1][q][0], v4y = v[t][1][q][1], v4z = v[t][1][q][2];
                    H4[q] = s4 + wi[t][q]*s1v[q];
                    float w1i = wi[t][2+q]*s1v[q];
                    V4[q][0] = v4x + w1i*uIx[t];
                    V4[q][1] = v4y + w1i*uIy[t];
                    V4[q][2] = v4z;
                    float dotc = v4x*ux + v4y*uy;
                    float base = wb0[q]*s4;
                    H3[q] = s[t][0][q] + base + wb2[q]*dotc;
                    H5[q] = s[t][2][q] + base - wb2[q]*dotc;
                    float cx = -v4z*uy, cy = v4z*ux, cz = v4x*uy - v4y*ux;
                    float y2x = dotc*ux - v4x*(1.f/3.f);
                    float y2y = dotc*uy - v4y*(1.f/3.f);
                    float y2z = -v4z*(1.f/3.f);
                    float sx = wb1[q]*s4;
                    V3[q][0] = v[t][0][q][0] + sx*ux + wb3[q]*cx + wb4[q]*y2x;
                    V3[q][1] = v[t][0][q][1] + sx*uy + wb3[q]*cy + wb4[q]*y2y;
                    V3[q][2] = v[t][0][q][2]         + wb3[q]*cz + wb4[q]*y2z;
                    V5[q][0] = v[t][2][q][0] - sx*ux - wb3[q]*cx + wb4[q]*y2x;
                    V5[q][1] = v[t][2][q][1] - sx*uy - wb3[q]*cy + wb4[q]*y2y;
                    V5[q][2] = v[t][2][q][2]         - wb3[q]*cz + wb4[q]*y2z;
                }
                *(float2*)&hb[0*52 + c0] = make_float2(H3[0], H3[1]);
                *(float2*)&hb[1*52 + c0] = make_float2(H4[0], H4[1]);
                *(float2*)&hb[2*52 + c0] = make_float2(H5[0], H5[1]);
                #pragma unroll
                for (int d = 0; d < 3; d++) {
                    *(float2*)&hb[156 + (0*3+d)*52 + c0] = make_float2(V3[0][d], V3[1][d]);
                    *(float2*)&hb[156 + (1*3+d)*52 + c0] = make_float2(V4[0][d], V4[1][d]);
                    *(float2*)&hb[156 + (2*3+d)*52 + c0] = make_float2(V5[0][d], V5[1][d]);
                }
            }
        }
        __syncthreads();   // Wr2s reads done block-wide; messages written
        // ---- Phase B staging: pair-transposed Ws/Wg/Wv ----
        {
            const float* gs = Ws + (size_t)l*CC*CC;
            const float* gg = Wg + (size_t)l*CC*CC;
            const float* gv = Wv + (size_t)l*CC*CC;
            for (int idx = tid; idx < CC*CC; idx += NTHREADS) {
                int c = idx/CC, j = idx - c*CC;
                int o = (c>>1)*100 + 2*j + (c&1);
                sm[WSS_OFF + o] = gs[idx];
                sm[WGS_OFF + o] = gg[idx];
                sm[WVS_OFF + o] = gv[idx];
            }
        }
        __syncthreads();
        // ---- node update with packed f32x2 FMA ----
        if (act) {
            const int wcol = 4*k;
            #pragma unroll 1
            for (int n = 0; n < 3; n++) {
                u64 aS[TRIPW][2], aG[TRIPW][2], aVx[TRIPW][2], aVy[TRIPW][2], aVz[TRIPW][2];
                #pragma unroll
                for (int t = 0; t < TRIPW; t++) {
                    aS[t][0]=aS[t][1]=aG[t][0]=aG[t][1]=0ull;
                    aVx[t][0]=aVx[t][1]=aVy[t][0]=aVy[t][1]=aVz[t][0]=aVz[t][1]=0ull;
                }
                #pragma unroll 1
                for (int g2 = 0; g2 < 13; g2++) {
                    const int p0 = 2*g2;
                    ulonglong2 ws0 = *(const ulonglong2*)&sm[WSS_OFF + p0*100 + wcol];
                    ulonglong2 ws1 = *(const ulonglong2*)&sm[WSS_OFF + (p0+1)*100 + wcol];
                    ulonglong2 wg0 = *(const ulonglong2*)&sm[WGS_OFF + p0*100 + wcol];
                    ulonglong2 wg1 = *(const ulonglong2*)&sm[WGS_OFF + (p0+1)*100 + wcol];
                    ulonglong2 wv0 = *(const ulonglong2*)&sm[WVS_OFF + p0*100 + wcol];
                    ulonglong2 wv1 = *(const ulonglong2*)&sm[WVS_OFF + (p0+1)*100 + wcol];
                    #pragma unroll
                    for (int t = 0; t < TRIPW; t++) {
                        const float* hb = hbW + t*HVT_TRIP;
                        ulonglong2 h2  = *(const ulonglong2*)&hb[n*52 + 4*g2];
                        ulonglong2 vx2 = *(const ulonglong2*)&hb[156 + (n*3+0)*52 + 4*g2];
                        ulonglong2 vy2 = *(const ulonglong2*)&hb[156 + (n*3+1)*52 + 4*g2];
                        ulonglong2 vz2 = *(const ulonglong2*)&hb[156 + (n*3+2)*52 + 4*g2];
                        aS[t][0]  = fma2(h2.x,  ws0.x, aS[t][0]);
                        aS[t][1]  = fma2(h2.x,  ws0.y, aS[t][1]);
                        aG[t][0]  = fma2(h2.x,  wg0.x, aG[t][0]);
                        aG[t][1]  = fma2(h2.x,  wg0.y, aG[t][1]);
                        aVx[t][0] = fma2(vx2.x, wv0.x, aVx[t][0]);
                        aVx[t][1] = fma2(vx2.x, wv0.y, aVx[t][1]);
                        aVy[t][0] = fma2(vy2.x, wv0.x, aVy[t][0]);
                        aVy[t][1] = fma2(vy2.x, wv0.y, aVy[t][1]);
                        aVz[t][0] = fma2(vz2.x, wv0.x, aVz[t][0]);
                        aVz[t][1] = fma2(vz2.x, wv0.y, aVz[t][1]);
                        aS[t][0]  = fma2(h2.y,  ws1.x, aS[t][0]);
                        aS[t][1]  = fma2(h2.y,  ws1.y, aS[t][1]);
                        aG[t][0]  = fma2(h2.y,  wg1.x, aG[t][0]);
                        aG[t][1]  = fma2(h2.y,  wg1.y, aG[t][1]);
                        aVx[t][0] = fma2(vx2.y, wv1.x, aVx[t][0]);
                        aVx[t][1] = fma2(vx2.y, wv1.y, aVx[t][1]);
                        aVy[t][0] = fma2(vy2.y, wv1.x, aVy[t][0]);
                        aVy[t][1] = fma2(vy2.y, wv1.y, aVy[t][1]);
                        aVz[t][0] = fma2(vz2.y, wv1.x, aVz[t][0]);
                        aVz[t][1] = fma2(vz2.y, wv1.y, aVz[t][1]);
                    }
                }
                #pragma unroll
                for (int t = 0; t < TRIPW; t++)
                    #pragma unroll
                    for (int q = 0; q < 2; q++) {
                        float2 rs = unpack2(aS[t][q]);
                        float2 rg = unpack2(aG[t][q]);
                        float2 rx = unpack2(aVx[t][q]);
                        float2 ry = unpack2(aVy[t][q]);
                        float2 rz = unpack2(aVz[t][q]);
                        float gg = sigmf(rg.x + rg.y);
                        s[t][n][q]    = siluf(rs.x + rs.y);
                        v[t][n][q][0] = (rx.x + rx.y)*gg;
                        v[t][n][q][1] = (ry.x + ry.y)*gg;
                        v[t][n][q][2] = (rz.x + rz.y)*gg;
                    }
            }
        }
    }

    // ---- epilogue ----
    float p[TRIPW][9];
    #pragma unroll
    for (int t = 0; t < TRIPW; t++)
        #pragma unroll
        for (int i = 0; i < 9; i++) p[t][i] = 0.f;
    if (act) {
        #pragma unroll
        for (int q = 0; q < 2; q++) {
            float wo = W_out[c0+q];
            #pragma unroll
            for (int t = 0; t < TRIPW; t++)
                #pragma unroll
                for (int n = 0; n < 3; n++)
                    #pragma unroll
                    for (int d = 0; d < 3; d++)
                        p[t][n*3+d] += wo*v[t][n][q][d];
        }
    }
    #pragma unroll
    for (int off = 16; off > 0; off >>= 1)
        #pragma unroll
        for (int t = 0; t < TRIPW; t++)
            #pragma unroll
            for (int i = 0; i < 9; i++)
                p[t][i] += __shfl_xor_sync(0xffffffffu, p[t][i], off);
    if (lane == 0) {
        #pragma unroll
        for (int t = 0; t < TRIPW; t++) {
            int g = gbase + t;
            int b = g >> 9;
            int tt = g & 511;
            float rx = p[t][0] + p[t][3] + p[t][6];
            float ry = p[t][1] + p[t][4] + p[t][7];
            float offx = -HALFBAR*u3x[t], offy = -HALFBAR*u3y[t];
            float rz = (offx*p[t][1] - offy*p[t][0]) - (offx*p[t][7] - offy*p[t][6]);
            float* o = outp + ((size_t)b*LL + (tt+1))*3;
            o[0] = rx; o[1] = ry; o[2] = rz;
        }
    }
}

// ---------------------------------------------------------------------------
extern "C" void kernel_launch(void* const* d_in, const int* in_sizes, int n_in,
                              void* d_out, int out_size)
{
    const float* y       = (const float*)d_in[0];
    const float* W_embed = (const float*)d_in[1];
    const float* Wr1     = (const float*)d_in[2];
    const float* br1     = (const float*)d_in[3];
    const float* Wr2     = (const float*)d_in[4];
    const float* Ws      = (const float*)d_in[5];
    const float* Wv      = (const float*)d_in[6];
    const float* Wg      = (const float*)d_in[7];
    const float* W_out   = (const float*)d_in[8];
    float* outp = (float*)d_out;

    cudaFuncSetAttribute(e3nn_main, cudaFuncAttributeMaxDynamicSharedMemorySize, SMEM_BYTES);

    cudaMemsetAsync(d_out, 0, (size_t)out_size*sizeof(float), 0);
    e3nn_precompute<<<1, 256>>>(W_embed, Wr1, br1, Wr2, Ws);
    e3nn_main<<<NBLOCKS, NTHREADS, SMEM_BYTES>>>(y, W_embed, Wr1, br1, Wr2,
                                                 Ws, Wv, Wg, W_out, outp);
}

// round 7
// speedup vs baseline: 1.4027x; 1.4027x over previous
#include <cuda_runtime.h>
#include <math.h>

// Problem constants
#define CC      50
#define HID     64
#define NB      10
#define NPATHS  5
#define NLAYERS 6
#define BB      64
#define LL      514
#define TT      512
#define NT      (BB*TT)
#define MAXR    0.06f
#define HALFBAR 0.05f
#define PI_F    3.14159265358979f

// Kernel config: 4 warps/block, 4 triplets per warp, 3 blocks/SM
#define TRIPW    4
#define WPB      4
#define NTHREADS 128
#define TPB      (WPB*TRIPW)      // 16
#define NBLOCKS  (NT/TPB)         // 2048

// Shared memory layout (float offsets)
// phase A: Wr1s [0,768), Wr2s(cols 0..99) [768,7168)
// phase B: Wss [0,2600) Wgs [2600,5200) Wvs [5200,7800) (rows 50,51 zeroed)
#define WSS_OFF    0
#define WGS_OFF    2600
#define WVS_OFF    5200
#define WR2_OFF    768
#define OFF_HVT    7800
#define HVT_TRIP   624            // 12 rows * 52 (3 H + 9 VT)
#define SMEM_FLOATS (OFF_HVT + TPB*HVT_TRIP)   // 17784
#define SMEM_BYTES (SMEM_FLOATS*4)             // 71136

__device__ float g_s1[NLAYERS][CC];
__device__ float g_wbar[NLAYERS][NPATHS*CC];

__device__ __forceinline__ float siluf(float x){ return x/(1.f+__expf(-x)); }
__device__ __forceinline__ float sigmf(float x){ return 1.f/(1.f+__expf(-x)); }

// ---------------------------------------------------------------------------
__global__ void e3nn_precompute(const float* __restrict__ W_embed,
                                const float* __restrict__ Wr1,
                                const float* __restrict__ br1,
                                const float* __restrict__ Wr2,
                                const float* __restrict__ Ws)
{
    __shared__ float s1[CC], s1n[CC], hid[HID], emb[NB+2];
    __shared__ float fc0s;
    int tid = threadIdx.x;
    if (tid < CC) s1[tid] = W_embed[tid] + W_embed[CC + tid];
    if (tid == 0) {
        const float r = HALFBAR;
        float tt = fminf(fmaxf(r/MAXR, 0.f), 1.f);
        float fc = 0.5f*(cosf(PI_F*tt) + 1.f);
        fc0s = fc;
        const float width = MAXR/(float)(NB-1);
        for (int i = 0; i < NB; i++) {
            float ci = MAXR*(float)i/(float)(NB-1);
            float d  = (r - ci)/width;
            emb[i]   = __expf(-d*d)*fc;
        }
        emb[NB]   = 0.f;
        emb[NB+1] = 1.f;
    }
    __syncthreads();
    for (int l = 0; l < NLAYERS; l++) {
        if (tid < CC) g_s1[l][tid] = s1[tid];
        if (tid < HID) {
            float acc = br1[l*HID + tid];
            #pragma unroll
            for (int i = 0; i < NB+2; i++) acc += emb[i]*Wr1[(l*(NB+2)+i)*HID + tid];
            hid[tid] = siluf(acc);
        }
        if (tid < CC) {
            float acc = 0.f;
            for (int c = 0; c < CC; c++) acc += s1[c]*Ws[(l*CC + c)*CC + tid];
            s1n[tid] = siluf(acc);
        }
        __syncthreads();
        if (tid < NPATHS*CC) {
            float acc = 0.f;
            for (int j = 0; j < HID; j++) acc += hid[j]*Wr2[(l*HID + j)*(NPATHS*CC) + tid];
            g_wbar[l][tid] = acc*fc0s;
        }
        if (tid < CC) s1[tid] = s1n[tid];
        __syncthreads();
    }
}

// ---------------------------------------------------------------------------
__global__ void __launch_bounds__(NTHREADS, 3) e3nn_main(
    const float* __restrict__ y,
    const float* __restrict__ W_embed,
    const float* __restrict__ Wr1,
    const float* __restrict__ br1,
    const float* __restrict__ Wr2,
    const float* __restrict__ Ws,
    const float* __restrict__ Wv,
    const float* __restrict__ Wg,
    const float* __restrict__ W_out,
    float* __restrict__ outp)
{
    extern __shared__ float sm[];
    const int tid  = threadIdx.x;
    const int w    = tid >> 5;
    const int lane = tid & 31;
    const int k    = lane;
    const bool act = (k < 25);
    const int c0   = 2*k;
    const int c1   = c0 + 1;
    const int k2c  = act ? (c0+1) : 0;

    const int gbase = blockIdx.x*TPB + w*TRIPW;
    float* hbW = sm + OFF_HVT + (w*TRIPW)*HVT_TRIP;

    // ---- geometry init: lanes 0..3 handle one triplet each; emb in regs ----
    float myUIx=0.f, myUIy=0.f, myU3x=0.f, myU3y=0.f, myFc=0.f;
    float eb[NB+2];
    #pragma unroll
    for (int i = 0; i < NB+2; i++) eb[i] = 0.f;
    if (lane < TRIPW) {
        int g = gbase + lane;
        int b = g >> 9;
        int t = g & 511;
        const float* yb = y + ((size_t)b*LL + t)*6;
        float p0x = yb[0],  p0y = yb[1];
        float p1x = yb[6],  p1y = yb[7];
        float a   = yb[8];
        float ex = p0x - p1x, ey = p0y - p1y;
        float r  = sqrtf(ex*ex + ey*ey);
        float inv = 1.f/(r + 1e-12f);
        myUIx = ex*inv; myUIy = ey*inv;
        myU3x = sinf(a); myU3y = -cosf(a);
        float tt = fminf(fmaxf(r/MAXR, 0.f), 1.f);
        myFc = 0.5f*(cosf(PI_F*tt) + 1.f);
        const float width = MAXR/(float)(NB-1);
        #pragma unroll
        for (int i = 0; i < NB; i++) {
            float ci = MAXR*(float)i/(float)(NB-1);
            float d  = (r - ci)/width;
            eb[i]    = __expf(-d*d)*myFc;
        }
        eb[NB]   = 1.f;
        eb[NB+1] = 0.f;
    }
    float uIx[TRIPW], uIy[TRIPW], u3x[TRIPW], u3y[TRIPW], fcT[TRIPW];
    #pragma unroll
    for (int t = 0; t < TRIPW; t++) {
        uIx[t] = __shfl_sync(0xffffffffu, myUIx, t);
        uIy[t] = __shfl_sync(0xffffffffu, myUIy, t);
        u3x[t] = __shfl_sync(0xffffffffu, myU3x, t);
        u3y[t] = __shfl_sync(0xffffffffu, myU3y, t);
        fcT[t] = __shfl_sync(0xffffffffu, myFc,  t);
    }

    // ---- register state ----
    float s[TRIPW][3][2];
    float v[TRIPW][3][2][3];
    #pragma unroll
    for (int t = 0; t < TRIPW; t++)
        #pragma unroll
        for (int n = 0; n < 3; n++)
            #pragma unroll
            for (int q = 0; q < 2; q++) {
                s[t][n][q] = 0.f;
                v[t][n][q][0] = v[t][n][q][1] = v[t][n][q][2] = 0.f;
            }
    if (act) {
        float e00 = W_embed[c0],      e01 = W_embed[c1];
        float e10 = W_embed[CC+c0],   e11 = W_embed[CC+c1];
        float e20 = W_embed[2*CC+c0], e21 = W_embed[2*CC+c1];
        #pragma unroll
        for (int t = 0; t < TRIPW; t++) {
            s[t][0][0] = e00 + e20;  s[t][0][1] = e01 + e21;
            s[t][1][0] = e00 + e10;  s[t][1][1] = e01 + e11;
            s[t][2][0] = e00 + e20;  s[t][2][1] = e01 + e21;
        }
    }

    for (int l = 0; l < NLAYERS; l++) {
        __syncthreads();
        // ---- Phase A staging: Wr1[l] (768) + Wr2[l][:,0:100] (6400) ----
        {
            const float4* s1p = (const float4*)(Wr1 + (size_t)l*(NB+2)*HID);
            float4* d1 = (float4*)sm;
            for (int i = tid; i < 192; i += NTHREADS) d1[i] = s1p[i];
            const float* src2 = Wr2 + (size_t)l*HID*(NPATHS*CC);
            float* dst2 = sm + WR2_OFF;
            for (int idx = tid; idx < HID*100; idx += NTHREADS) {
                int j = idx/100, o = idx - j*100;
                dst2[idx] = src2[j*(NPATHS*CC) + o];
            }
        }
        __syncthreads();
        // ---- hid per triplet (emb via shfl; HIDS aliased at hbW[0,256)) ----
        {
            float a0[TRIPW], a1[TRIPW];
            float b0 = br1[l*HID + lane];
            float b1 = br1[l*HID + lane + 32];
            #pragma unroll
            for (int t = 0; t < TRIPW; t++) { a0[t] = b0; a1[t] = b1; }
            #pragma unroll
            for (int i = 0; i < NB+2; i++) {
                float w0v = sm[i*HID + lane];
                float w1v = sm[i*HID + lane + 32];
                float ev  = eb[i];
                #pragma unroll
                for (int t = 0; t < TRIPW; t++) {
                    float e = __shfl_sync(0xffffffffu, ev, t);
                    a0[t] += e*w0v;
                    a1[t] += e*w1v;
                }
            }
            #pragma unroll
            for (int t = 0; t < TRIPW; t++) {
                hbW[t*64 + lane]      = siluf(a0[t]);
                hbW[t*64 + lane + 32] = siluf(a1[t]);
            }
        }
        __syncwarp();
        // ---- inter-edge weights (paths 0,1; v_src=0 kills paths 2..4) ----
        float wi[TRIPW][4];
        #pragma unroll
        for (int t = 0; t < TRIPW; t++)
            wi[t][0]=wi[t][1]=wi[t][2]=wi[t][3]=0.f;
        if (act) {
            #pragma unroll 1
            for (int j4 = 0; j4 < HID; j4 += 4) {
                float4 hv[TRIPW];
                #pragma unroll
                for (int t = 0; t < TRIPW; t++)
                    hv[t] = *(const float4*)&hbW[t*64 + j4];
                #pragma unroll
                for (int jo = 0; jo < 4; jo++) {
                    float2 wa = *(const float2*)&sm[WR2_OFF + (j4+jo)*100 + c0];
                    float2 wc = *(const float2*)&sm[WR2_OFF + (j4+jo)*100 + 50 + c0];
                    #pragma unroll
                    for (int t = 0; t < TRIPW; t++) {
                        float hj = (jo==0)?hv[t].x:(jo==1)?hv[t].y:(jo==2)?hv[t].z:hv[t].w;
                        wi[t][0] += hj*wa.x;
                        wi[t][1] += hj*wa.y;
                        wi[t][2] += hj*wc.x;
                        wi[t][3] += hj*wc.y;
                    }
                }
            }
            #pragma unroll
            for (int t = 0; t < TRIPW; t++) {
                wi[t][0]*=fcT[t]; wi[t][1]*=fcT[t]; wi[t][2]*=fcT[t]; wi[t][3]*=fcT[t];
            }
        }
        __syncwarp();   // HIDS reads done before messages overwrite hbW
        // ---- pad slots of hb rows -> 0 (HIDS aliasing dirtied them) ----
        #pragma unroll
        for (int i = lane; i < 96; i += 32) {
            int t  = i/24;
            int rm = i - t*24;
            hbW[t*HVT_TRIP + (rm>>1)*52 + 50 + (rm&1)] = 0.f;
        }
        // ---- messages -> hb ----
        if (act) {
            float wb0[2], wb1[2], wb2[2], wb3[2], wb4[2], s1v[2];
            #pragma unroll
            for (int q = 0; q < 2; q++) {
                int cq = c0 + q;
                wb0[q] = g_wbar[l][cq];
                wb1[q] = g_wbar[l][50+cq];
                wb2[q] = g_wbar[l][100+cq];
                wb3[q] = g_wbar[l][150+cq];
                wb4[q] = g_wbar[l][200+cq];
                s1v[q] = g_s1[l][cq];
            }
            #pragma unroll
            for (int t = 0; t < TRIPW; t++) {
                float* hb = hbW + t*HVT_TRIP;
                float H3[2], H4[2], H5[2];
                float V3[2][3], V4[2][3], V5[2][3];
                float ux = u3x[t], uy = u3y[t];
                #pragma unroll
                for (int q = 0; q < 2; q++) {
                    float s4  = s[t][1][q];
                    float v4x = v[t][1][q][0], v4y = v[t][1][q][1], v4z = v[t][1][q][2];
                    H4[q] = s4 + wi[t][q]*s1v[q];
                    float w1i = wi[t][2+q]*s1v[q];
                    V4[q][0] = v4x + w1i*uIx[t];
                    V4[q][1] = v4y + w1i*uIy[t];
                    V4[q][2] = v4z;
                    float dotc = v4x*ux + v4y*uy;
                    float base = wb0[q]*s4;
                    H3[q] = s[t][0][q] + base + wb2[q]*dotc;
                    H5[q] = s[t][2][q] + base - wb2[q]*dotc;
                    float cx = -v4z*uy, cy = v4z*ux, cz = v4x*uy - v4y*ux;
                    float y2x = dotc*ux - v4x*(1.f/3.f);
                    float y2y = dotc*uy - v4y*(1.f/3.f);
                    float y2z = -v4z*(1.f/3.f);
                    float sx = wb1[q]*s4;
                    V3[q][0] = v[t][0][q][0] + sx*ux + wb3[q]*cx + wb4[q]*y2x;
                    V3[q][1] = v[t][0][q][1] + sx*uy + wb3[q]*cy + wb4[q]*y2y;
                    V3[q][2] = v[t][0][q][2]         + wb3[q]*cz + wb4[q]*y2z;
                    V5[q][0] = v[t][2][q][0] - sx*ux - wb3[q]*cx + wb4[q]*y2x;
                    V5[q][1] = v[t][2][q][1] - sx*uy - wb3[q]*cy + wb4[q]*y2y;
                    V5[q][2] = v[t][2][q][2]         - wb3[q]*cz + wb4[q]*y2z;
                }
                *(float2*)&hb[0*52 + c0] = make_float2(H3[0], H3[1]);
                *(float2*)&hb[1*52 + c0] = make_float2(H4[0], H4[1]);
                *(float2*)&hb[2*52 + c0] = make_float2(H5[0], H5[1]);
                #pragma unroll
                for (int d = 0; d < 3; d++) {
                    *(float2*)&hb[156 + (0*3+d)*52 + c0] = make_float2(V3[0][d], V3[1][d]);
                    *(float2*)&hb[156 + (1*3+d)*52 + c0] = make_float2(V4[0][d], V4[1][d]);
                    *(float2*)&hb[156 + (2*3+d)*52 + c0] = make_float2(V5[0][d], V5[1][d]);
                }
            }
        }
        __syncthreads();   // Wr2s reads done block-wide; messages written
        // ---- Phase B staging: contiguous float4 copies of Ws/Wg/Wv ----
        {
            const float4* sa = (const float4*)(Ws + (size_t)l*CC*CC);
            const float4* sb = (const float4*)(Wg + (size_t)l*CC*CC);
            const float4* sc = (const float4*)(Wv + (size_t)l*CC*CC);
            float4* da = (float4*)(sm + WSS_OFF);
            float4* db = (float4*)(sm + WGS_OFF);
            float4* dc = (float4*)(sm + WVS_OFF);
            for (int i = tid; i < 625; i += NTHREADS) { da[i]=sa[i]; db[i]=sb[i]; dc[i]=sc[i]; }
            for (int i = tid; i < 100; i += NTHREADS) {
                sm[WSS_OFF + 2500 + i] = 0.f;
                sm[WGS_OFF + 2500 + i] = 0.f;
                sm[WVS_OFF + 2500 + i] = 0.f;
            }
        }
        __syncthreads();
        // ---- node update: s=silu(H@Ws), gate=sigm(H@Wg), v=(VT@Wv)*gate ----
        if (act) {
            #pragma unroll 1
            for (int n = 0; n < 3; n++) {
                float aS[TRIPW][2], aG[TRIPW][2], aVx[TRIPW][2], aVy[TRIPW][2], aVz[TRIPW][2];
                #pragma unroll
                for (int t = 0; t < TRIPW; t++) {
                    aS[t][0]=aS[t][1]=aG[t][0]=aG[t][1]=0.f;
                    aVx[t][0]=aVx[t][1]=aVy[t][0]=aVy[t][1]=aVz[t][0]=aVz[t][1]=0.f;
                }
                #pragma unroll 1
                for (int cg = 0; cg < 52; cg += 4) {
                    float2 wsv[4], wgv[4], wvv[4];
                    #pragma unroll
                    for (int i = 0; i < 4; i++) {
                        wsv[i] = *(const float2*)&sm[WSS_OFF + (cg+i)*CC + c0];
                        wgv[i] = *(const float2*)&sm[WGS_OFF + (cg+i)*CC + c0];
                        wvv[i] = *(const float2*)&sm[WVS_OFF + (cg+i)*CC + c0];
                    }
                    #pragma unroll
                    for (int t = 0; t < TRIPW; t++) {
                        const float* hb = hbW + t*HVT_TRIP;
                        float4 h4  = *(const float4*)&hb[n*52 + cg];
                        float4 vx4 = *(const float4*)&hb[156 + (n*3+0)*52 + cg];
                        float4 vy4 = *(const float4*)&hb[156 + (n*3+1)*52 + cg];
                        float4 vz4 = *(const float4*)&hb[156 + (n*3+2)*52 + cg];
                        #pragma unroll
                        for (int i = 0; i < 4; i++) {
                            float hc  = (i==0)?h4.x :(i==1)?h4.y :(i==2)?h4.z :h4.w;
                            float vxc = (i==0)?vx4.x:(i==1)?vx4.y:(i==2)?vx4.z:vx4.w;
                            float vyc = (i==0)?vy4.x:(i==1)?vy4.y:(i==2)?vy4.z:vy4.w;
                            float vzc = (i==0)?vz4.x:(i==1)?vz4.y:(i==2)?vz4.z:vz4.w;
                            aS[t][0]  += hc*wsv[i].x;  aS[t][1]  += hc*wsv[i].y;
                            aG[t][0]  += hc*wgv[i].x;  aG[t][1]  += hc*wgv[i].y;
                            aVx[t][0] += vxc*wvv[i].x; aVx[t][1] += vxc*wvv[i].y;
                            aVy[t][0] += vyc*wvv[i].x; aVy[t][1] += vyc*wvv[i].y;
                            aVz[t][0] += vzc*wvv[i].x; aVz[t][1] += vzc*wvv[i].y;
                        }
                    }
                }
                #pragma unroll
                for (int t = 0; t < TRIPW; t++)
                    #pragma unroll
                    for (int q = 0; q < 2; q++) {
                        float gg = sigmf(aG[t][q]);
                        s[t][n][q]    = siluf(aS[t][q]);
                        v[t][n][q][0] = aVx[t][q]*gg;
                        v[t][n][q][1] = aVy[t][q]*gg;
                        v[t][n][q][2] = aVz[t][q]*gg;
                    }
            }
        }
    }

    // ---- epilogue ----
    float p[TRIPW][9];
    #pragma unroll
    for (int t = 0; t < TRIPW; t++)
        #pragma unroll
        for (int i = 0; i < 9; i++) p[t][i] = 0.f;
    if (act) {
        #pragma unroll
        for (int q = 0; q < 2; q++) {
            float wo = W_out[c0+q];
            #pragma unroll
            for (int t = 0; t < TRIPW; t++)
                #pragma unroll
                for (int n = 0; n < 3; n++)
                    #pragma unroll
                    for (int d = 0; d < 3; d++)
                        p[t][n*3+d] += wo*v[t][n][q][d];
        }
    }
    #pragma unroll
    for (int off = 16; off > 0; off >>= 1)
        #pragma unroll
        for (int t = 0; t < TRIPW; t++)
            #pragma unroll
            for (int i = 0; i < 9; i++)
                p[t][i] += __shfl_xor_sync(0xffffffffu, p[t][i], off);
    if (lane == 0) {
        #pragma unroll
        for (int t = 0; t < TRIPW; t++) {
            int g = gbase + t;
            int b = g >> 9;
            int tt = g & 511;
            float rx = p[t][0] + p[t][3] + p[t][6];
            float ry = p[t][1] + p[t][4] + p[t][7];
            float offx = -HALFBAR*u3x[t], offy = -HALFBAR*u3y[t];
            float rz = (offx*p[t][1] - offy*p[t][0]) - (offx*p[t][7] - offy*p[t][6]);
            float* o = outp + ((size_t)b*LL + (tt+1))*3;
            o[0] = rx; o[1] = ry; o[2] = rz;
        }
    }
}

// ---------------------------------------------------------------------------
extern "C" void kernel_launch(void* const* d_in, const int* in_sizes, int n_in,
                              void* d_out, int out_size)
{
    const float* y       = (const float*)d_in[0];
    const float* W_embed = (const float*)d_in[1];
    const float* Wr1     = (const float*)d_in[2];
    const float* br1     = (const float*)d_in[3];
    const float* Wr2     = (const float*)d_in[4];
    const float* Ws      = (const float*)d_in[5];
    const float* Wv      = (const float*)d_in[6];
    const float* Wg      = (const float*)d_in[7];
    const float* W_out   = (const float*)d_in[8];
    float* outp = (float*)d_out;

    cudaFuncSetAttribute(e3nn_main, cudaFuncAttributeMaxDynamicSharedMemorySize, SMEM_BYTES);

    cudaMemsetAsync(d_out, 0, (size_t)out_size*sizeof(float), 0);
    e3nn_precompute<<<1, 256>>>(W_embed, Wr1, br1, Wr2, Ws);
    e3nn_main<<<NBLOCKS, NTHREADS, SMEM_BYTES>>>(y, W_embed, Wr1, br1, Wr2,
                                                 Ws, Wv, Wg, W_out, outp);
}

// round 8
// speedup vs baseline: 1.9385x; 1.3820x over previous
#include <cuda_runtime.h>
#include <math.h>

// Problem constants
#define CC      50
#define HID     64
#define NB      10
#define NPATHS  5
#define NLAYERS 6
#define BB      64
#define LL      514
#define TT      512
#define NT      (BB*TT)
#define MAXR    0.06f
#define HALFBAR 0.05f
#define PI_F    3.14159265358979f

// wi(r) interpolation table
#define TKNOTS  256           // intervals over [0, MAXR]
#define TROWS   260           // rows: knot -1 .. 258 (clamped duplicates)

// Kernel config: 4 warps/block, 4 triplets per warp, 3 blocks/SM
#define TRIPW    4
#define WPB      4
#define NTHREADS 128
#define TPB      (WPB*TRIPW)      // 16
#define NBLOCKS  (NT/TPB)         // 2048

// Shared memory layout (float offsets)
// Wss [0,2600) Wgs [2600,5200) Wvs [5200,7800) (rows 50,51 zeroed each stage)
#define WSS_OFF    0
#define WGS_OFF    2600
#define WVS_OFF    5200
#define OFF_HVT    7800
#define HVT_TRIP   624            // 12 rows * 52 (3 H + 9 VT)
#define SMEM_FLOATS (OFF_HVT + TPB*HVT_TRIP)   // 17784
#define SMEM_BYTES (SMEM_FLOATS*4)             // 71136

__device__ float g_s1[NLAYERS][CC];
__device__ float g_wbar[NLAYERS][NPATHS*CC];
// wi table: [layer][row][lane-packed 100]: for lane k, 4 floats =
// (path0 c=2k, path0 c=2k+1, path1 c=2k, path1 c=2k+1), fcut folded in.
__device__ float g_witab[NLAYERS][TROWS][100];

__device__ __forceinline__ float siluf(float x){ return x/(1.f+__expf(-x)); }
__device__ __forceinline__ float sigmf(float x){ return 1.f/(1.f+__expf(-x)); }

// ---------------------------------------------------------------------------
// Precompute per-layer global constants (node-1 s trajectory + intra-edge w)
// ---------------------------------------------------------------------------
__global__ void e3nn_precompute(const float* __restrict__ W_embed,
                                const float* __restrict__ Wr1,
                                const float* __restrict__ br1,
                                const float* __restrict__ Wr2,
                                const float* __restrict__ Ws)
{
    __shared__ float s1[CC], s1n[CC], hid[HID], emb[NB+2];
    __shared__ float fc0s;
    int tid = threadIdx.x;
    if (tid < CC) s1[tid] = W_embed[tid] + W_embed[CC + tid];
    if (tid == 0) {
        const float r = HALFBAR;
        float tt = fminf(fmaxf(r/MAXR, 0.f), 1.f);
        float fc = 0.5f*(cosf(PI_F*tt) + 1.f);
        fc0s = fc;
        const float width = MAXR/(float)(NB-1);
        for (int i = 0; i < NB; i++) {
            float ci = MAXR*(float)i/(float)(NB-1);
            float d  = (r - ci)/width;
            emb[i]   = __expf(-d*d)*fc;
        }
        emb[NB]   = 0.f;
        emb[NB+1] = 1.f;
    }
    __syncthreads();
    for (int l = 0; l < NLAYERS; l++) {
        if (tid < CC) g_s1[l][tid] = s1[tid];
        if (tid < HID) {
            float acc = br1[l*HID + tid];
            #pragma unroll
            for (int i = 0; i < NB+2; i++) acc += emb[i]*Wr1[(l*(NB+2)+i)*HID + tid];
            hid[tid] = siluf(acc);
        }
        if (tid < CC) {
            float acc = 0.f;
            for (int c = 0; c < CC; c++) acc += s1[c]*Ws[(l*CC + c)*CC + tid];
            s1n[tid] = siluf(acc);
        }
        __syncthreads();
        if (tid < NPATHS*CC) {
            float acc = 0.f;
            for (int j = 0; j < HID; j++) acc += hid[j]*Wr2[(l*HID + j)*(NPATHS*CC) + tid];
            g_wbar[l][tid] = acc*fc0s;
        }
        if (tid < CC) s1[tid] = s1n[tid];
        __syncthreads();
    }
}

// ---------------------------------------------------------------------------
// Build the wi(r) table: exact MLP evaluated at 257 knots per layer.
// grid = NLAYERS*TROWS blocks of 128 threads.
// ---------------------------------------------------------------------------
__global__ void e3nn_build_table(const float* __restrict__ Wr1,
                                 const float* __restrict__ br1,
                                 const float* __restrict__ Wr2)
{
    const int l   = blockIdx.x / TROWS;
    const int row = blockIdx.x - l*TROWS;
    int knot = row - 1;
    knot = knot < 0 ? 0 : (knot > TKNOTS ? TKNOTS : knot);
    const float r = (float)knot * (MAXR/(float)TKNOTS);
    __shared__ float emb[NB+2], hid[HID], fcs;
    const int tid = threadIdx.x;
    if (tid == 0) {
        float tt = fminf(fmaxf(r/MAXR, 0.f), 1.f);
        float fc = 0.5f*(cosf(PI_F*tt) + 1.f);
        fcs = fc;
        const float width = MAXR/(float)(NB-1);
        for (int i = 0; i < NB; i++) {
            float ci = MAXR*(float)i/(float)(NB-1);
            float d  = (r - ci)/width;
            emb[i]   = __expf(-d*d)*fc;
        }
        emb[NB]   = 1.f;   // inter edge_attr = one_hot(0)
        emb[NB+1] = 0.f;
    }
    __syncthreads();
    if (tid < HID) {
        float acc = br1[l*HID + tid];
        #pragma unroll
        for (int i = 0; i < NB+2; i++) acc += emb[i]*Wr1[(l*(NB+2)+i)*HID + tid];
        hid[tid] = siluf(acc);
    }
    __syncthreads();
    if (tid < 100) {
        int k = tid >> 2, sub = tid & 3;
        int ch = (sub < 2) ? (2*k + sub) : (50 + 2*k + (sub-2));
        float acc = 0.f;
        for (int j = 0; j < HID; j++)
            acc += hid[j]*Wr2[(l*HID + j)*(NPATHS*CC) + ch];
        g_witab[l][row][tid] = acc*fcs;
    }
}

// ---------------------------------------------------------------------------
// Main fused kernel
// ---------------------------------------------------------------------------
__global__ void __launch_bounds__(NTHREADS, 3) e3nn_main(
    const float* __restrict__ y,
    const float* __restrict__ W_embed,
    const float* __restrict__ Ws,
    const float* __restrict__ Wv,
    const float* __restrict__ Wg,
    const float* __restrict__ W_out,
    float* __restrict__ outp)
{
    extern __shared__ float sm[];
    const int tid  = threadIdx.x;
    const int w    = tid >> 5;
    const int lane = tid & 31;
    const int k    = lane;
    const bool act = (k < 25);
    const int c0   = 2*k;
    const int c1   = c0 + 1;

    const int gbase = blockIdx.x*TPB + w*TRIPW;
    float* hbW = sm + OFF_HVT + (w*TRIPW)*HVT_TRIP;

    // ---- zero entire H/VT region once (pads stay 0 forever) ----
    for (int i = tid; i < TPB*HVT_TRIP; i += NTHREADS) sm[OFF_HVT + i] = 0.f;

    // ---- geometry init: lanes 0..3 handle one triplet each ----
    float myUIx=0.f, myUIy=0.f, myU3x=0.f, myU3y=0.f, myR=1e9f;
    if (lane < TRIPW) {
        int g = gbase + lane;
        int b = g >> 9;
        int t = g & 511;
        const float* yb = y + ((size_t)b*LL + t)*6;
        float p0x = yb[0],  p0y = yb[1];
        float p1x = yb[6],  p1y = yb[7];
        float a   = yb[8];
        float ex = p0x - p1x, ey = p0y - p1y;
        float r  = sqrtf(ex*ex + ey*ey);
        float inv = 1.f/(r + 1e-12f);
        myUIx = ex*inv; myUIy = ey*inv;
        myU3x = sinf(a); myU3y = -cosf(a);
        myR = r;
    }
    float uIx[TRIPW], uIy[TRIPW], u3x[TRIPW], u3y[TRIPW], rT[TRIPW];
    #pragma unroll
    for (int t = 0; t < TRIPW; t++) {
        uIx[t] = __shfl_sync(0xffffffffu, myUIx, t);
        uIy[t] = __shfl_sync(0xffffffffu, myUIy, t);
        u3x[t] = __shfl_sync(0xffffffffu, myU3x, t);
        u3y[t] = __shfl_sync(0xffffffffu, myU3y, t);
        rT[t]  = __shfl_sync(0xffffffffu, myR,  t);
    }

    // ---- register state ----
    float s[TRIPW][3][2];
    float v[TRIPW][3][2][3];
    #pragma unroll
    for (int t = 0; t < TRIPW; t++)
        #pragma unroll
        for (int n = 0; n < 3; n++)
            #pragma unroll
            for (int q = 0; q < 2; q++) {
                s[t][n][q] = 0.f;
                v[t][n][q][0] = v[t][n][q][1] = v[t][n][q][2] = 0.f;
            }
    if (act) {
        float e00 = W_embed[c0],      e01 = W_embed[c1];
        float e10 = W_embed[CC+c0],   e11 = W_embed[CC+c1];
        float e20 = W_embed[2*CC+c0], e21 = W_embed[2*CC+c1];
        #pragma unroll
        for (int t = 0; t < TRIPW; t++) {
            s[t][0][0] = e00 + e20;  s[t][0][1] = e01 + e21;
            s[t][1][0] = e00 + e10;  s[t][1][1] = e01 + e11;
            s[t][2][0] = e00 + e20;  s[t][2][1] = e01 + e21;
        }
    }

    for (int l = 0; l < NLAYERS; l++) {
        __syncthreads();   // prior GEMM done reading weight buf (l=0: HVT zeroed)
        // ---- stage Ws/Wg/Wv (contiguous float4) + zero pad rows 50,51 ----
        {
            const float4* sa = (const float4*)(Ws + (size_t)l*CC*CC);
            const float4* sb = (const float4*)(Wg + (size_t)l*CC*CC);
            const float4* sc = (const float4*)(Wv + (size_t)l*CC*CC);
            float4* da = (float4*)(sm + WSS_OFF);
            float4* db = (float4*)(sm + WGS_OFF);
            float4* dc = (float4*)(sm + WVS_OFF);
            for (int i = tid; i < 625; i += NTHREADS) { da[i]=sa[i]; db[i]=sb[i]; dc[i]=sc[i]; }
            for (int i = tid; i < 100; i += NTHREADS) {
                sm[WSS_OFF + 2500 + i] = 0.f;
                sm[WGS_OFF + 2500 + i] = 0.f;
                sm[WVS_OFF + 2500 + i] = 0.f;
            }
        }
        // ---- inter-edge weights via Catmull-Rom table lookup ----
        float wi[TRIPW][4];
        if (act) {
            #pragma unroll
            for (int t = 0; t < TRIPW; t++) {
                float xr = rT[t]*((float)TKNOTS/MAXR);
                float valid = (xr < (float)TKNOTS) ? 1.f : 0.f;
                xr = fminf(xr, (float)TKNOTS - 0.001f);
                float jf = floorf(xr);
                int j = (int)jf;
                float u = xr - jf;
                float u2 = u*u, u3 = u2*u;
                float cw0 = 0.5f*(-u + 2.f*u2 - u3);
                float cw1 = 0.5f*(2.f - 5.f*u2 + 3.f*u3);
                float cw2 = 0.5f*(u + 4.f*u2 - 3.f*u3);
                float cw3 = 0.5f*(-u2 + u3);
                const float* tb = &g_witab[l][j][4*k];
                float4 r0 = *(const float4*)(tb);
                float4 r1 = *(const float4*)(tb + 100);
                float4 r2 = *(const float4*)(tb + 200);
                float4 r3 = *(const float4*)(tb + 300);
                wi[t][0] = valid*(cw0*r0.x + cw1*r1.x + cw2*r2.x + cw3*r3.x);
                wi[t][1] = valid*(cw0*r0.y + cw1*r1.y + cw2*r2.y + cw3*r3.y);
                wi[t][2] = valid*(cw0*r0.z + cw1*r1.z + cw2*r2.z + cw3*r3.z);
                wi[t][3] = valid*(cw0*r0.w + cw1*r1.w + cw2*r2.w + cw3*r3.w);
            }
        }
        // ---- messages -> hb (warp-local; block barrier below orders it) ----
        if (act) {
            float wb0[2], wb1[2], wb2[2], wb3[2], wb4[2], s1v[2];
            #pragma unroll
            for (int q = 0; q < 2; q++) {
                int cq = c0 + q;
                wb0[q] = g_wbar[l][cq];
                wb1[q] = g_wbar[l][50+cq];
                wb2[q] = g_wbar[l][100+cq];
                wb3[q] = g_wbar[l][150+cq];
                wb4[q] = g_wbar[l][200+cq];
                s1v[q] = g_s1[l][cq];
            }
            #pragma unroll
            for (int t = 0; t < TRIPW; t++) {
                float* hb = hbW + t*HVT_TRIP;
                float H3[2], H4[2], H5[2];
                float V3[2][3], V4[2][3], V5[2][3];
                float ux = u3x[t], uy = u3y[t];
                #pragma unroll
                for (int q = 0; q < 2; q++) {
                    float s4  = s[t][1][q];
                    float v4x = v[t][1][q][0], v4y = v[t][1][q][1], v4z = v[t][1][q][2];
                    H4[q] = s4 + wi[t][q]*s1v[q];
                    float w1i = wi[t][2+q]*s1v[q];
                    V4[q][0] = v4x + w1i*uIx[t];
                    V4[q][1] = v4y + w1i*uIy[t];
                    V4[q][2] = v4z;
                    float dotc = v4x*ux + v4y*uy;
                    float base = wb0[q]*s4;
                    H3[q] = s[t][0][q] + base + wb2[q]*dotc;
                    H5[q] = s[t][2][q] + base - wb2[q]*dotc;
                    float cx = -v4z*uy, cy = v4z*ux, cz = v4x*uy - v4y*ux;
                    float y2x = dotc*ux - v4x*(1.f/3.f);
                    float y2y = dotc*uy - v4y*(1.f/3.f);
                    float y2z = -v4z*(1.f/3.f);
                    float sx = wb1[q]*s4;
                    V3[q][0] = v[t][0][q][0] + sx*ux + wb3[q]*cx + wb4[q]*y2x;
                    V3[q][1] = v[t][0][q][1] + sx*uy + wb3[q]*cy + wb4[q]*y2y;
                    V3[q][2] = v[t][0][q][2]         + wb3[q]*cz + wb4[q]*y2z;
                    V5[q][0] = v[t][2][q][0] - sx*ux - wb3[q]*cx + wb4[q]*y2x;
                    V5[q][1] = v[t][2][q][1] - sx*uy - wb3[q]*cy + wb4[q]*y2y;
                    V5[q][2] = v[t][2][q][2]         - wb3[q]*cz + wb4[q]*y2z;
                }
                *(float2*)&hb[0*52 + c0] = make_float2(H3[0], H3[1]);
                *(float2*)&hb[1*52 + c0] = make_float2(H4[0], H4[1]);
                *(float2*)&hb[2*52 + c0] = make_float2(H5[0], H5[1]);
                #pragma unroll
                for (int d = 0; d < 3; d++) {
                    *(float2*)&hb[156 + (0*3+d)*52 + c0] = make_float2(V3[0][d], V3[1][d]);
                    *(float2*)&hb[156 + (1*3+d)*52 + c0] = make_float2(V4[0][d], V4[1][d]);
                    *(float2*)&hb[156 + (2*3+d)*52 + c0] = make_float2(V5[0][d], V5[1][d]);
                }
            }
        }
        __syncthreads();   // weights staged + hb written
        // ---- node update: s=silu(H@Ws), gate=sigm(H@Wg), v=(VT@Wv)*gate ----
        if (act) {
            #pragma unroll 1
            for (int n = 0; n < 3; n++) {
                float aS[TRIPW][2], aG[TRIPW][2], aVx[TRIPW][2], aVy[TRIPW][2], aVz[TRIPW][2];
                #pragma unroll
                for (int t = 0; t < TRIPW; t++) {
                    aS[t][0]=aS[t][1]=aG[t][0]=aG[t][1]=0.f;
                    aVx[t][0]=aVx[t][1]=aVy[t][0]=aVy[t][1]=aVz[t][0]=aVz[t][1]=0.f;
                }
                #pragma unroll 1
                for (int cg = 0; cg < 52; cg += 4) {
                    float2 wsv[4], wgv[4], wvv[4];
                    #pragma unroll
                    for (int i = 0; i < 4; i++) {
                        wsv[i] = *(const float2*)&sm[WSS_OFF + (cg+i)*CC + c0];
                        wgv[i] = *(const float2*)&sm[WGS_OFF + (cg+i)*CC + c0];
                        wvv[i] = *(const float2*)&sm[WVS_OFF + (cg+i)*CC + c0];
                    }
                    #pragma unroll
                    for (int t = 0; t < TRIPW; t++) {
                        const float* hb = hbW + t*HVT_TRIP;
                        float4 h4  = *(const float4*)&hb[n*52 + cg];
                        float4 vx4 = *(const float4*)&hb[156 + (n*3+0)*52 + cg];
                        float4 vy4 = *(const float4*)&hb[156 + (n*3+1)*52 + cg];
                        float4 vz4 = *(const float4*)&hb[156 + (n*3+2)*52 + cg];
                        #pragma unroll
                        for (int i = 0; i < 4; i++) {
                            float hc  = (i==0)?h4.x :(i==1)?h4.y :(i==2)?h4.z :h4.w;
                            float vxc = (i==0)?vx4.x:(i==1)?vx4.y:(i==2)?vx4.z:vx4.w;
                            float vyc = (i==0)?vy4.x:(i==1)?vy4.y:(i==2)?vy4.z:vy4.w;
                            float vzc = (i==0)?vz4.x:(i==1)?vz4.y:(i==2)?vz4.z:vz4.w;
                            aS[t][0]  += hc*wsv[i].x;  aS[t][1]  += hc*wsv[i].y;
                            aG[t][0]  += hc*wgv[i].x;  aG[t][1]  += hc*wgv[i].y;
                            aVx[t][0] += vxc*wvv[i].x; aVx[t][1] += vxc*wvv[i].y;
                            aVy[t][0] += vyc*wvv[i].x; aVy[t][1] += vyc*wvv[i].y;
                            aVz[t][0] += vzc*wvv[i].x; aVz[t][1] += vzc*wvv[i].y;
                        }
                    }
                }
                #pragma unroll
                for (int t = 0; t < TRIPW; t++)
                    #pragma unroll
                    for (int q = 0; q < 2; q++) {
                        float gg = sigmf(aG[t][q]);
                        s[t][n][q]    = siluf(aS[t][q]);
                        v[t][n][q][0] = aVx[t][q]*gg;
                        v[t][n][q][1] = aVy[t][q]*gg;
                        v[t][n][q][2] = aVz[t][q]*gg;
                    }
            }
        }
    }

    // ---- epilogue ----
    float p[TRIPW][9];
    #pragma unroll
    for (int t = 0; t < TRIPW; t++)
        #pragma unroll
        for (int i = 0; i < 9; i++) p[t][i] = 0.f;
    if (act) {
        #pragma unroll
        for (int q = 0; q < 2; q++) {
            float wo = W_out[c0+q];
            #pragma unroll
            for (int t = 0; t < TRIPW; t++)
                #pragma unroll
                for (int n = 0; n < 3; n++)
                    #pragma unroll
                    for (int d = 0; d < 3; d++)
                        p[t][n*3+d] += wo*v[t][n][q][d];
        }
    }
    #pragma unroll
    for (int off = 16; off > 0; off >>= 1)
        #pragma unroll
        for (int t = 0; t < TRIPW; t++)
            #pragma unroll
            for (int i = 0; i < 9; i++)
                p[t][i] += __shfl_xor_sync(0xffffffffu, p[t][i], off);
    if (lane == 0) {
        #pragma unroll
        for (int t = 0; t < TRIPW; t++) {
            int g = gbase + t;
            int b = g >> 9;
            int tt = g & 511;
            float rx = p[t][0] + p[t][3] + p[t][6];
            float ry = p[t][1] + p[t][4] + p[t][7];
            float offx = -HALFBAR*u3x[t], offy = -HALFBAR*u3y[t];
            float rz = (offx*p[t][1] - offy*p[t][0]) - (offx*p[t][7] - offy*p[t][6]);
            float* o = outp + ((size_t)b*LL + (tt+1))*3;
            o[0] = rx; o[1] = ry; o[2] = rz;
        }
    }
}

// ---------------------------------------------------------------------------
extern "C" void kernel_launch(void* const* d_in, const int* in_sizes, int n_in,
                              void* d_out, int out_size)
{
    const float* y       = (const float*)d_in[0];
    const float* W_embed = (const float*)d_in[1];
    const float* Wr1     = (const float*)d_in[2];
    const float* br1     = (const float*)d_in[3];
    const float* Wr2     = (const float*)d_in[4];
    const float* Ws      = (const float*)d_in[5];
    const float* Wv      = (const float*)d_in[6];
    const float* Wg      = (const float*)d_in[7];
    const float* W_out   = (const float*)d_in[8];
    float* outp = (float*)d_out;

    cudaFuncSetAttribute(e3nn_main, cudaFuncAttributeMaxDynamicSharedMemorySize, SMEM_BYTES);

    cudaMemsetAsync(d_out, 0, (size_t)out_size*sizeof(float), 0);
    e3nn_precompute<<<1, 256>>>(W_embed, Wr1, br1, Wr2, Ws);
    e3nn_build_table<<<NLAYERS*TROWS, 128>>>(Wr1, br1, Wr2);
    e3nn_main<<<NBLOCKS, NTHREADS, SMEM_BYTES>>>(y, W_embed, Ws, Wv, Wg, W_out, outp);
}